// round 14
// baseline (speedup 1.0000x reference)
#include <cuda_runtime.h>
#include <cuda_fp16.h>
#include <cstdint>

// Problem constants
#define B_ 4
#define D_ 512
#define T_ 2048
#define H_ 8
#define DH_ 64
#define BH_ 32        // B*H
#define NBH_ 96       // 3*B*H
#define NEG_SLOPE 0.2f
#define EPS_ 1e-6f
#define LOG2E_ 1.44269504088896f

// ---------------------------------------------------------------------------
// Scratch (__device__ globals; allocation-free rule)
// ---------------------------------------------------------------------------
__device__ float g_ssp[NBH_ * 16 * 64];             // rms partials [nbh][tblk][dh]
// fp16 operands (all RAW, unscaled; scales applied inside attention)
__device__ __half g_q[(size_t)BH_ * T_ * DH_];      // Q raw fp16 [bh][t][dh]
__device__ __half g_k[(size_t)BH_ * T_ * DH_];      // K raw fp16
__device__ __half g_vt[(size_t)BH_ * DH_ * T_];     // V^T raw fp16
__device__ __half g_xh[(size_t)B_ * T_ * D_];       // [b][t][d] lrelu'd
__device__ __half g_wh[(size_t)24 * DH_ * D_];      // [n*8+h][dh][d]

// ---------------------------------------------------------------------------
// PTX helpers
// ---------------------------------------------------------------------------
__device__ __forceinline__ uint32_t smem_u32(const void* p) {
    uint32_t a;
    asm("{ .reg .u64 t; cvta.to.shared.u64 t, %1; cvt.u32.u64 %0, t; }"
        : "=r"(a) : "l"(p));
    return a;
}
__device__ __forceinline__ void cp16(uint32_t dst, const void* src) {
    asm volatile("cp.async.cg.shared.global [%0], [%1], 16;"
                 :: "r"(dst), "l"(src));
}
#define CP_COMMIT() asm volatile("cp.async.commit_group;" ::: "memory")
#define CP_WAIT1()  asm volatile("cp.async.wait_group 1;" ::: "memory")
#define CP_WAIT0()  asm volatile("cp.async.wait_group 0;" ::: "memory")

#define LDSM4(r0, r1, r2, r3, addr) \
    asm volatile("ldmatrix.sync.aligned.m8n8.x4.shared.b16 {%0,%1,%2,%3}, [%4];" \
        : "=r"(r0), "=r"(r1), "=r"(r2), "=r"(r3) : "r"(addr))

#define MMA16816H(c, a, b0, b1) \
    asm volatile("mma.sync.aligned.m16n8k16.row.col.f32.f16.f16.f32 " \
        "{%0,%1,%2,%3}, {%4,%5,%6,%7}, {%8,%9}, {%0,%1,%2,%3};" \
        : "+f"((c)[0]), "+f"((c)[1]), "+f"((c)[2]), "+f"((c)[3]) \
        : "r"((a)[0]), "r"((a)[1]), "r"((a)[2]), "r"((a)[3]), "r"(b0), "r"(b1))

// pack (x -> low, y -> high) as f16x2
__device__ __forceinline__ uint32_t packh2(float x, float y) {
    uint32_t r;
    asm("cvt.rn.f16x2.f32 %0, %1, %2;" : "=r"(r) : "f"(y), "f"(x));
    return r;
}
__device__ __forceinline__ float ex2f(float x) {
    float r;
    asm("ex2.approx.f32 %0, %1;" : "=f"(r) : "f"(x));
    return r;
}

// ---------------------------------------------------------------------------
// Kernel 1a: x convert — leaky-relu + fp16 + transpose to [b][t][d]
// grid (T/64, D/64, B), block 256
// ---------------------------------------------------------------------------
__global__ __launch_bounds__(256) void xconv_kernel(const float* __restrict__ x)
{
    __shared__ unsigned short shi[64][66];
    const int t0 = blockIdx.x * 64, d0 = blockIdx.y * 64, b = blockIdx.z;
    const int tid = threadIdx.x;
    const float* xb = x + (size_t)b * D_ * T_;

#pragma unroll
    for (int k = 0; k < 16; k++) {
        int idx = tid + k * 256;
        int r = idx >> 6, c = idx & 63;        // r = d row, c = t col
        float v = xb[(size_t)(d0 + r) * T_ + t0 + c];
        v = (v >= 0.f) ? v : NEG_SLOPE * v;
        shi[c][r] = __half_as_ushort(__float2half_rn(v));   // transposed [t][d]
    }
    __syncthreads();
#pragma unroll
    for (int k = 0; k < 8; k++) {
        int idx = tid + k * 256;
        int t = idx >> 5, u = idx & 31;
        size_t go = ((size_t)b * T_ + t0 + t) * D_ + d0 + u * 2;
        *(uint32_t*)(g_xh + go) = shi[t][u * 2] | ((uint32_t)shi[t][u * 2 + 1] << 16);
    }
}

// ---------------------------------------------------------------------------
// Kernel 1b: weight convert — fp16 + transpose to [nh][dh][d]; grid 24
// ---------------------------------------------------------------------------
__global__ __launch_bounds__(256) void wconv_kernel(const float* __restrict__ w)
{
    __shared__ unsigned short shi[64][66];
    const int nh = blockIdx.x, tid = threadIdx.x;
    const float* wb = w + (size_t)nh * D_ * DH_;

    for (int d0 = 0; d0 < D_; d0 += 64) {
#pragma unroll
        for (int k = 0; k < 16; k++) {
            int idx = tid + k * 256;
            int r = idx >> 6, c = idx & 63;
            shi[c][r] = __half_as_ushort(__float2half_rn(wb[(size_t)(d0 + r) * DH_ + c]));
        }
        __syncthreads();
#pragma unroll
        for (int k = 0; k < 8; k++) {
            int idx = tid + k * 256;
            int dh = idx >> 5, u = idx & 31;
            size_t go = ((size_t)nh * DH_ + dh) * D_ + d0 + u * 2;
            *(uint32_t*)(g_wh + go) = shi[dh][u * 2] | ((uint32_t)shi[dh][u * 2 + 1] << 16);
        }
        __syncthreads();
    }
}

// ---------------------------------------------------------------------------
// Kernel 1c: QKV projection, 2 heads per CTA (128x128 tile) + fused RMS
// grid (T/128, 48): y = n*16 + b*4 + hpair;  block 256 (8 warps x 16 rows)
// ---------------------------------------------------------------------------
#define QG_SA(buf) ((buf) * 18432)           // A fp16 (128 x 144B)
#define QG_SB(buf) (36864 + (buf) * 18432)   // B fp16 (128 x 144B)
#define QG_TOTAL 73728

__global__ __launch_bounds__(256, 2) void qkv_mma_kernel()
{
    extern __shared__ char sm[];
    const uint32_t smb = smem_u32(sm);
    const int tid = threadIdx.x, wid = tid >> 5, lane = tid & 31;
    const int yi = blockIdx.y;                   // n*16 + b*4 + hpair
    const int n = yi >> 4, b = (yi >> 2) & 3, h0 = (yi & 3) * 2;
    const int t0 = blockIdx.x * 128;

    const __half* xh = g_xh + ((size_t)b * T_ + t0) * D_;
    const __half* wh = g_wh + (size_t)(n * 8 + h0) * DH_ * D_;  // 128 rows = 2 heads

    auto load_a = [&](int buf, int d0) {
#pragma unroll
        for (int m = 0; m < 4; m++) {
            int cid = tid + m * 256;
            int row = cid >> 3, c = cid & 7;
            cp16(smb + QG_SA(buf) + row * 144 + c * 16,
                 xh + (size_t)row * D_ + d0 + c * 8);
        }
    };
    auto load_b = [&](int buf, int d0) {
#pragma unroll
        for (int m = 0; m < 4; m++) {
            int cid = tid + m * 256;
            int row = cid >> 3, c = cid & 7;   // row 0..127: 2 heads x 64 dh
            cp16(smb + QG_SB(buf) + row * 144 + c * 16,
                 wh + (size_t)row * D_ + d0 + c * 8);
        }
    };

    load_a(0, 0); load_b(0, 0);
    CP_COMMIT();

    const int laneRowA = lane & 15;
    const int laneColA = (lane >> 4) * 8;
    const int laneRowB = ((lane >> 4) & 1) * 8 + (lane & 7);
    const int laneColB = ((lane >> 3) & 1) * 8;
    const int fr = lane >> 2, fc = (lane & 3) * 2;

    float acc[16][4] = {};

    for (int i = 0; i < 8; i++) {
        const int buf = i & 1;
        if (i + 1 < 8) { load_a(buf ^ 1, (i + 1) * 64); load_b(buf ^ 1, (i + 1) * 64); CP_COMMIT(); }
        if (i + 1 < 8) { CP_WAIT1(); } else { CP_WAIT0(); }
        __syncthreads();

#pragma unroll
        for (int ks = 0; ks < 4; ks++) {
            uint32_t ah[4];
            uint32_t abase = smb + QG_SA(buf) + (16 * wid + laneRowA) * 144
                           + (ks * 16 + laneColA) * 2;
            LDSM4(ah[0], ah[1], ah[2], ah[3], abase);
#pragma unroll
            for (int p = 0; p < 8; p++) {
                uint32_t h0r, h1r, h2r, h3r;
                uint32_t bbase = smb + QG_SB(buf) + (16 * p + laneRowB) * 144
                               + (ks * 16 + laneColB) * 2;
                LDSM4(h0r, h1r, h2r, h3r, bbase);
                MMA16816H(acc[2 * p],     ah, h0r, h1r);
                MMA16816H(acc[2 * p + 1], ah, h2r, h3r);
            }
        }
        __syncthreads();
    }

    const int lrow = 16 * wid + fr;              // local row 0..127

    // ---- epilogue: raw fp16 outputs (cols 0..63 -> h0, 64..127 -> h0+1) ----
    if (n < 2) {
        __half* base = (n == 0 ? g_q : g_k);
        __half* dst0 = base + ((size_t)(b * 8 + h0) * T_ + t0 + lrow) * DH_;
        __half* dst1 = base + ((size_t)(b * 8 + h0 + 1) * T_ + t0 + lrow) * DH_;
#pragma unroll
        for (int nb = 0; nb < 8; nb++) {
            int col = nb * 8 + fc;
            *(uint32_t*)(dst0 + col)           = packh2(acc[nb][0], acc[nb][1]);
            *(uint32_t*)(dst0 + 8 * DH_ + col) = packh2(acc[nb][2], acc[nb][3]);
            *(uint32_t*)(dst1 + col)           = packh2(acc[nb + 8][0], acc[nb + 8][1]);
            *(uint32_t*)(dst1 + 8 * DH_ + col) = packh2(acc[nb + 8][2], acc[nb + 8][3]);
        }
    } else {
        // transpose both heads to [dh][t] via smem (stride 136 ushorts)
        unsigned short* sv = (unsigned short*)sm;    // [128][136]
#pragma unroll
        for (int nb = 0; nb < 16; nb++) {
            int c = nb * 8 + fc;
            sv[c * 136 + lrow]           = __half_as_ushort(__float2half_rn(acc[nb][0]));
            sv[(c + 1) * 136 + lrow]     = __half_as_ushort(__float2half_rn(acc[nb][1]));
            sv[c * 136 + lrow + 8]       = __half_as_ushort(__float2half_rn(acc[nb][2]));
            sv[(c + 1) * 136 + lrow + 8] = __half_as_ushort(__float2half_rn(acc[nb][3]));
        }
        __syncthreads();
#pragma unroll
        for (int m = 0; m < 8; m++) {
            int e = tid + m * 256;               // 2048 uint4 = 128 rows x 16
            int row = e >> 4, q4 = (e & 15) * 8;
            int bh = b * 8 + h0 + (row >> 6), dh = row & 63;
            uint4 v = *(uint4*)(sv + row * 136 + q4);
            *(uint4*)(g_vt + ((size_t)bh * DH_ + dh) * T_ + t0 + q4) = v;
        }
    }

    // ---- fused RMS partials (fp32 accumulators) ----
    float loc[32];
#pragma unroll
    for (int nb = 0; nb < 16; nb++) {
        loc[nb * 2 + 0] = acc[nb][0] * acc[nb][0] + acc[nb][2] * acc[nb][2];
        loc[nb * 2 + 1] = acc[nb][1] * acc[nb][1] + acc[nb][3] * acc[nb][3];
    }
#pragma unroll
    for (int off = 4; off <= 16; off <<= 1)
#pragma unroll
        for (int k = 0; k < 32; k++)
            loc[k] += __shfl_xor_sync(0xffffffffu, loc[k], off);

    __syncthreads();
    float* red = (float*)sm;              // [8][128]
    if (lane < 4) {
#pragma unroll
        for (int nb = 0; nb < 16; nb++) {
            red[wid * 128 + nb * 8 + fc + 0] = loc[nb * 2 + 0];
            red[wid * 128 + nb * 8 + fc + 1] = loc[nb * 2 + 1];
        }
    }
    __syncthreads();
    if (tid < 128) {
        float s = 0.f;
#pragma unroll
        for (int w = 0; w < 8; w++) s += red[w * 128 + tid];
        int nbh = n * 32 + b * 8 + h0 + (tid >> 6);
        g_ssp[(nbh * 16 + blockIdx.x) * 64 + (tid & 63)] = s;
    }
}

// ---------------------------------------------------------------------------
// Kernel 2: mma.sync flash attention — 4 warps x 32 query rows
//   per-key-chunk fused S -> exp2 -> PV (small transient sAcc);
//   K/V fragments shared across 2 row-groups (MMA:LDSM = 4:1)
// grid (T/128, 32), block 128
// ---------------------------------------------------------------------------
#define TQ 128
#define TN 64
#define NIT (T_ / TN)
#define SM_Q 0                           // 128 x 144B = 18432 (fp16)
#define SM_KV(s) (18432 + (s) * 18432)   // K (64x144) + V (64x144) per stage
#define SM_SC 73728                      // cs[64] + rv[64] floats
#define SM_TOTAL 74240

__global__ __launch_bounds__(128) void attn_mma_kernel(float* __restrict__ out,
                                                       const float* __restrict__ norm_w)
{
    extern __shared__ char sm[];
    const uint32_t smb = smem_u32(sm);
    const int tid = threadIdx.x, wid = tid >> 5, lane = tid & 31;
    const int bh = blockIdx.y, t0 = blockIdx.x * TQ;

    const __half* qp = g_q + ((size_t)bh * T_ + t0) * DH_;
    const __half* kp = g_k + (size_t)bh * T_ * DH_;
    const __half* vp = g_vt + (size_t)bh * DH_ * T_;

    auto load_kv = [&](int stage, int j0) {
#pragma unroll
        for (int m = 0; m < 4; m++) {
            int cid = tid + m * 128;
            int row = cid >> 3, c = cid & 7;
            cp16(smb + SM_KV(stage) + row * 144 + c * 16,
                 kp + (size_t)(j0 + row) * DH_ + c * 8);
            cp16(smb + SM_KV(stage) + 9216 + row * 144 + c * 16,
                 vp + (size_t)row * T_ + j0 + c * 8);
        }
    };

    // prologue loads
#pragma unroll
    for (int m = 0; m < 8; m++) {
        int cid = tid + m * 128;
        int row = cid >> 3, c = cid & 7;
        cp16(smb + SM_Q + row * 144 + c * 16, qp + (size_t)row * DH_ + c * 8);
    }
    load_kv(0, 0);
    CP_COMMIT();
    load_kv(1, TN);
    CP_COMMIT();

    // scale tables from RMS partials (overlaps cp.async latency)
    float* scs = (float*)(sm + SM_SC);        // [64] combined QK scale
    float* rvs = scs + 64;                    // [64] V scale
    if (tid < 64) {
        float nw = norm_w[0];
        float sq = 0.f, sk = 0.f, sv = 0.f;
#pragma unroll
        for (int sl = 0; sl < 16; sl++) {
            sq += g_ssp[((0 * BH_ + bh) * 16 + sl) * 64 + tid];
            sk += g_ssp[((1 * BH_ + bh) * 16 + sl) * 64 + tid];
            sv += g_ssp[((2 * BH_ + bh) * 16 + sl) * 64 + tid];
        }
        float rq = nw * rsqrtf(sq * (1.f / T_) + EPS_);
        float rk = nw * rsqrtf(sk * (1.f / T_) + EPS_);
        scs[tid] = rq * rk * 0.125f * LOG2E_;
        rvs[tid] = nw * rsqrtf(sv * (1.f / T_) + EPS_);
    }

    const int laneRow = ((lane >> 4) & 1) * 8 + (lane & 7);
    const int laneCol = ((lane >> 3) & 1) * 8;
    const int fr = lane >> 2;
    const int fc = (lane & 3) * 2;

    float oAcc[2][8][4] = {};
    float lr[2][2] = {};
    uint32_t qh[2][4][4];                  // [row-group][dh-chunk][4]

    for (int i = 0; i < NIT; i++) {
        if (i + 1 < NIT) { CP_WAIT1(); } else { CP_WAIT0(); }
        __syncthreads();     // tile i ready; also orders scs/rvs writes (i==0)

        if (i + 2 < NIT) { load_kv((i + 2) % 3, (i + 2) * TN); CP_COMMIT(); }

        if (i == 0) {
#pragma unroll
            for (int g = 0; g < 2; g++) {
                const int r = 32 * wid + 16 * g + fr;
#pragma unroll
                for (int ks = 0; ks < 4; ks++) {
                    qh[g][ks][0] = *(const uint32_t*)(sm + SM_Q + r * 144 + (fc + 16 * ks) * 2);
                    qh[g][ks][1] = *(const uint32_t*)(sm + SM_Q + (r + 8) * 144 + (fc + 16 * ks) * 2);
                    qh[g][ks][2] = *(const uint32_t*)(sm + SM_Q + r * 144 + (fc + 8 + 16 * ks) * 2);
                    qh[g][ks][3] = *(const uint32_t*)(sm + SM_Q + (r + 8) * 144 + (fc + 8 + 16 * ks) * 2);
                    // fold combined per-dh scale into Q fragments (once per CTA)
#pragma unroll
                    for (int j = 0; j < 4; j++) {
                        int dh0 = ((j < 2) ? fc : fc + 8) + 16 * ks;
                        float2 c01 = *(float2*)&scs[dh0];
                        __half2 hv = *(__half2*)&qh[g][ks][j];
                        float2 f = __half22float2(hv);
                        qh[g][ks][j] = packh2(f.x * c01.x, f.y * c01.y);
                    }
                }
            }
        }

        const uint32_t kvb = smb + SM_KV(i % 3);

        // per-key-chunk fused S -> exp2 -> PV
#pragma unroll
        for (int p = 0; p < 4; p++) {
            float s[2][2][4] = {};           // [row-group][key-half][4]
#pragma unroll
            for (int ks = 0; ks < 4; ks++) {
                uint32_t b0, b1, b2, b3;
                uint32_t base = kvb + (16 * p + laneRow) * 144 + (16 * ks + laneCol) * 2;
                LDSM4(b0, b1, b2, b3, base);
                MMA16816H(s[0][0], qh[0][ks], b0, b1);
                MMA16816H(s[0][1], qh[0][ks], b2, b3);
                MMA16816H(s[1][0], qh[1][ks], b0, b1);
                MMA16816H(s[1][1], qh[1][ks], b2, b3);
            }

            uint32_t aP[2][4];
#pragma unroll
            for (int g = 0; g < 2; g++) {
                float e00 = ex2f(s[g][0][0]), e01 = ex2f(s[g][0][1]);
                float e02 = ex2f(s[g][0][2]), e03 = ex2f(s[g][0][3]);
                float e10 = ex2f(s[g][1][0]), e11 = ex2f(s[g][1][1]);
                float e12 = ex2f(s[g][1][2]), e13 = ex2f(s[g][1][3]);
                lr[g][0] += e00 + e01 + e10 + e11;
                lr[g][1] += e02 + e03 + e12 + e13;
                aP[g][0] = packh2(e00, e01);
                aP[g][1] = packh2(e02, e03);
                aP[g][2] = packh2(e10, e11);
                aP[g][3] = packh2(e12, e13);
            }

#pragma unroll
            for (int j = 0; j < 4; j++) {
                uint32_t v0, v1, v2, v3;
                uint32_t base = kvb + 9216 + (16 * j + laneRow) * 144
                              + (16 * p + laneCol) * 2;
                LDSM4(v0, v1, v2, v3, base);
                MMA16816H(oAcc[0][2 * j],     aP[0], v0, v1);
                MMA16816H(oAcc[0][2 * j + 1], aP[0], v2, v3);
                MMA16816H(oAcc[1][2 * j],     aP[1], v0, v1);
                MMA16816H(oAcc[1][2 * j + 1], aP[1], v2, v3);
            }
        }
    }

#pragma unroll
    for (int g = 0; g < 2; g++) {
#pragma unroll
        for (int hh = 0; hh < 2; hh++) {
            lr[g][hh] += __shfl_xor_sync(0xffffffffu, lr[g][hh], 1);
            lr[g][hh] += __shfl_xor_sync(0xffffffffu, lr[g][hh], 2);
        }
    }

    __syncthreads();
    float* Ot = (float*)sm;              // [64][132]  (disjoint from SM_SC)
#pragma unroll
    for (int g = 0; g < 2; g++) {
        const float inv0 = 1.f / lr[g][0], inv1 = 1.f / lr[g][1];
        const int rlo = 32 * wid + 16 * g + fr, rhi = rlo + 8;
#pragma unroll
        for (int nb = 0; nb < 8; nb++) {
            int c = nb * 8 + fc;
            float rv0 = rvs[c], rv1 = rvs[c + 1];
            Ot[c * 132 + rlo]       = oAcc[g][nb][0] * inv0 * rv0;
            Ot[(c + 1) * 132 + rlo] = oAcc[g][nb][1] * inv0 * rv1;
            Ot[c * 132 + rhi]       = oAcc[g][nb][2] * inv1 * rv0;
            Ot[(c + 1) * 132 + rhi] = oAcc[g][nb][3] * inv1 * rv1;
        }
    }
    __syncthreads();

    const int b_ = bh >> 3, h_ = bh & 7;
    float* ob = out + (size_t)b_ * D_ * T_ + (size_t)h_ * 64 * T_ + t0;
#pragma unroll
    for (int k = 0; k < 16; k++) {
        int idx = tid + k * 128;
        int dh = idx >> 5, c4 = idx & 31;
        float4 v = *(float4*)&Ot[dh * 132 + c4 * 4];
        *(float4*)(ob + (size_t)dh * T_ + c4 * 4) = v;
    }
}

// ---------------------------------------------------------------------------
extern "C" void kernel_launch(void* const* d_in, const int* in_sizes, int n_in,
                              void* d_out, int out_size)
{
    const float* x      = (const float*)d_in[0];
    const float* qkv    = (const float*)d_in[1];
    const float* norm_w = (const float*)d_in[2];
    float* out = (float*)d_out;
    (void)in_sizes; (void)n_in; (void)out_size;

    cudaFuncSetAttribute(attn_mma_kernel, cudaFuncAttributeMaxDynamicSharedMemorySize,
                         SM_TOTAL);
    cudaFuncSetAttribute(qkv_mma_kernel, cudaFuncAttributeMaxDynamicSharedMemorySize,
                         QG_TOTAL);

    xconv_kernel<<<dim3(T_ / 64, D_ / 64, B_), 256>>>(x);
    wconv_kernel<<<24, 256>>>(qkv);
    qkv_mma_kernel<<<dim3(T_ / 128, 48), 256, QG_TOTAL>>>();
    attn_mma_kernel<<<dim3(T_ / TQ, BH_), 128, SM_TOTAL>>>(out, norm_w);
}

// round 16
// speedup vs baseline: 1.0694x; 1.0694x over previous
#include <cuda_runtime.h>
#include <cuda_fp16.h>
#include <cstdint>

// Problem constants
#define B_ 4
#define D_ 512
#define T_ 2048
#define H_ 8
#define DH_ 64
#define BH_ 32        // B*H
#define NBH_ 96       // 3*B*H
#define NEG_SLOPE 0.2f
#define EPS_ 1e-6f
#define LOG2E_ 1.44269504088896f

// ---------------------------------------------------------------------------
// Scratch (__device__ globals; allocation-free rule)
// ---------------------------------------------------------------------------
__device__ float g_ssp[NBH_ * 16 * 64];             // rms partials [nbh][tblk][dh]
// fp16 operands (all RAW, unscaled; scales applied inside attention)
__device__ __half g_q[(size_t)BH_ * T_ * DH_];      // Q raw fp16 [bh][t][dh]
__device__ __half g_k[(size_t)BH_ * T_ * DH_];      // K raw fp16
__device__ __half g_vt[(size_t)BH_ * DH_ * T_];     // V^T raw fp16
__device__ __half g_xh[(size_t)B_ * T_ * D_];       // [b][t][d] lrelu'd
__device__ __half g_wh[(size_t)24 * DH_ * D_];      // [n*8+h][dh][d]

// ---------------------------------------------------------------------------
// PTX helpers
// ---------------------------------------------------------------------------
__device__ __forceinline__ uint32_t smem_u32(const void* p) {
    uint32_t a;
    asm("{ .reg .u64 t; cvta.to.shared.u64 t, %1; cvt.u32.u64 %0, t; }"
        : "=r"(a) : "l"(p));
    return a;
}
__device__ __forceinline__ void cp16(uint32_t dst, const void* src) {
    asm volatile("cp.async.cg.shared.global [%0], [%1], 16;"
                 :: "r"(dst), "l"(src));
}
#define CP_COMMIT() asm volatile("cp.async.commit_group;" ::: "memory")
#define CP_WAIT1()  asm volatile("cp.async.wait_group 1;" ::: "memory")
#define CP_WAIT0()  asm volatile("cp.async.wait_group 0;" ::: "memory")

#define LDSM4(r0, r1, r2, r3, addr) \
    asm volatile("ldmatrix.sync.aligned.m8n8.x4.shared.b16 {%0,%1,%2,%3}, [%4];" \
        : "=r"(r0), "=r"(r1), "=r"(r2), "=r"(r3) : "r"(addr))

#define MMA16816H(c, a, b0, b1) \
    asm volatile("mma.sync.aligned.m16n8k16.row.col.f32.f16.f16.f32 " \
        "{%0,%1,%2,%3}, {%4,%5,%6,%7}, {%8,%9}, {%0,%1,%2,%3};" \
        : "+f"((c)[0]), "+f"((c)[1]), "+f"((c)[2]), "+f"((c)[3]) \
        : "r"((a)[0]), "r"((a)[1]), "r"((a)[2]), "r"((a)[3]), "r"(b0), "r"(b1))

// pack (x -> low, y -> high) as f16x2
__device__ __forceinline__ uint32_t packh2(float x, float y) {
    uint32_t r;
    asm("cvt.rn.f16x2.f32 %0, %1, %2;" : "=r"(r) : "f"(y), "f"(x));
    return r;
}
__device__ __forceinline__ float ex2f(float x) {
    float r;
    asm("ex2.approx.f32 %0, %1;" : "=f"(r) : "f"(x));
    return r;
}

// ---------------------------------------------------------------------------
// Kernel 1a: x convert — leaky-relu + fp16 + transpose to [b][t][d]
// grid (T/64, D/64, B), block 256
// ---------------------------------------------------------------------------
__global__ __launch_bounds__(256) void xconv_kernel(const float* __restrict__ x)
{
    __shared__ unsigned short shi[64][66];
    const int t0 = blockIdx.x * 64, d0 = blockIdx.y * 64, b = blockIdx.z;
    const int tid = threadIdx.x;
    const float* xb = x + (size_t)b * D_ * T_;

#pragma unroll
    for (int k = 0; k < 16; k++) {
        int idx = tid + k * 256;
        int r = idx >> 6, c = idx & 63;        // r = d row, c = t col
        float v = xb[(size_t)(d0 + r) * T_ + t0 + c];
        v = (v >= 0.f) ? v : NEG_SLOPE * v;
        shi[c][r] = __half_as_ushort(__float2half_rn(v));   // transposed [t][d]
    }
    __syncthreads();
#pragma unroll
    for (int k = 0; k < 8; k++) {
        int idx = tid + k * 256;
        int t = idx >> 5, u = idx & 31;
        size_t go = ((size_t)b * T_ + t0 + t) * D_ + d0 + u * 2;
        *(uint32_t*)(g_xh + go) = shi[t][u * 2] | ((uint32_t)shi[t][u * 2 + 1] << 16);
    }
}

// ---------------------------------------------------------------------------
// Kernel 1b: weight convert — fp16 + transpose to [nh][dh][d]; grid 24
// ---------------------------------------------------------------------------
__global__ __launch_bounds__(256) void wconv_kernel(const float* __restrict__ w)
{
    __shared__ unsigned short shi[64][66];
    const int nh = blockIdx.x, tid = threadIdx.x;
    const float* wb = w + (size_t)nh * D_ * DH_;

    for (int d0 = 0; d0 < D_; d0 += 64) {
#pragma unroll
        for (int k = 0; k < 16; k++) {
            int idx = tid + k * 256;
            int r = idx >> 6, c = idx & 63;
            shi[c][r] = __half_as_ushort(__float2half_rn(wb[(size_t)(d0 + r) * DH_ + c]));
        }
        __syncthreads();
#pragma unroll
        for (int k = 0; k < 8; k++) {
            int idx = tid + k * 256;
            int dh = idx >> 5, u = idx & 31;
            size_t go = ((size_t)nh * DH_ + dh) * D_ + d0 + u * 2;
            *(uint32_t*)(g_wh + go) = shi[dh][u * 2] | ((uint32_t)shi[dh][u * 2 + 1] << 16);
        }
        __syncthreads();
    }
}

// ---------------------------------------------------------------------------
// Kernel 1c: QKV projection, 2 heads per CTA (128x128 tile) + fused RMS
// grid (T/128, 48): y = n*16 + b*4 + hpair;  block 256 (8 warps x 16 rows)
// ---------------------------------------------------------------------------
#define QG_SA(buf) ((buf) * 18432)           // A fp16 (128 x 144B)
#define QG_SB(buf) (36864 + (buf) * 18432)   // B fp16 (128 x 144B)
#define QG_TOTAL 73728

__global__ __launch_bounds__(256, 2) void qkv_mma_kernel()
{
    extern __shared__ char sm[];
    const uint32_t smb = smem_u32(sm);
    const int tid = threadIdx.x, wid = tid >> 5, lane = tid & 31;
    const int yi = blockIdx.y;                   // n*16 + b*4 + hpair
    const int n = yi >> 4, b = (yi >> 2) & 3, h0 = (yi & 3) * 2;
    const int t0 = blockIdx.x * 128;

    const __half* xh = g_xh + ((size_t)b * T_ + t0) * D_;
    const __half* wh = g_wh + (size_t)(n * 8 + h0) * DH_ * D_;  // 128 rows = 2 heads

    auto load_a = [&](int buf, int d0) {
#pragma unroll
        for (int m = 0; m < 4; m++) {
            int cid = tid + m * 256;
            int row = cid >> 3, c = cid & 7;
            cp16(smb + QG_SA(buf) + row * 144 + c * 16,
                 xh + (size_t)row * D_ + d0 + c * 8);
        }
    };
    auto load_b = [&](int buf, int d0) {
#pragma unroll
        for (int m = 0; m < 4; m++) {
            int cid = tid + m * 256;
            int row = cid >> 3, c = cid & 7;   // row 0..127: 2 heads x 64 dh
            cp16(smb + QG_SB(buf) + row * 144 + c * 16,
                 wh + (size_t)row * D_ + d0 + c * 8);
        }
    };

    load_a(0, 0); load_b(0, 0);
    CP_COMMIT();

    const int laneRowA = lane & 15;
    const int laneColA = (lane >> 4) * 8;
    const int laneRowB = ((lane >> 4) & 1) * 8 + (lane & 7);
    const int laneColB = ((lane >> 3) & 1) * 8;
    const int fr = lane >> 2, fc = (lane & 3) * 2;

    float acc[16][4] = {};

    for (int i = 0; i < 8; i++) {
        const int buf = i & 1;
        if (i + 1 < 8) { load_a(buf ^ 1, (i + 1) * 64); load_b(buf ^ 1, (i + 1) * 64); CP_COMMIT(); }
        if (i + 1 < 8) { CP_WAIT1(); } else { CP_WAIT0(); }
        __syncthreads();

#pragma unroll
        for (int ks = 0; ks < 4; ks++) {
            uint32_t ah[4];
            uint32_t abase = smb + QG_SA(buf) + (16 * wid + laneRowA) * 144
                           + (ks * 16 + laneColA) * 2;
            LDSM4(ah[0], ah[1], ah[2], ah[3], abase);
#pragma unroll
            for (int p = 0; p < 8; p++) {
                uint32_t h0r, h1r, h2r, h3r;
                uint32_t bbase = smb + QG_SB(buf) + (16 * p + laneRowB) * 144
                               + (ks * 16 + laneColB) * 2;
                LDSM4(h0r, h1r, h2r, h3r, bbase);
                MMA16816H(acc[2 * p],     ah, h0r, h1r);
                MMA16816H(acc[2 * p + 1], ah, h2r, h3r);
            }
        }
        __syncthreads();
    }

    const int lrow = 16 * wid + fr;              // local row 0..127

    // ---- epilogue: raw fp16 outputs (cols 0..63 -> h0, 64..127 -> h0+1) ----
    if (n < 2) {
        __half* base = (n == 0 ? g_q : g_k);
        __half* dst0 = base + ((size_t)(b * 8 + h0) * T_ + t0 + lrow) * DH_;
        __half* dst1 = base + ((size_t)(b * 8 + h0 + 1) * T_ + t0 + lrow) * DH_;
#pragma unroll
        for (int nb = 0; nb < 8; nb++) {
            int col = nb * 8 + fc;
            *(uint32_t*)(dst0 + col)           = packh2(acc[nb][0], acc[nb][1]);
            *(uint32_t*)(dst0 + 8 * DH_ + col) = packh2(acc[nb][2], acc[nb][3]);
            *(uint32_t*)(dst1 + col)           = packh2(acc[nb + 8][0], acc[nb + 8][1]);
            *(uint32_t*)(dst1 + 8 * DH_ + col) = packh2(acc[nb + 8][2], acc[nb + 8][3]);
        }
    } else {
        // transpose both heads to [dh][t] via smem (stride 136 ushorts)
        unsigned short* sv = (unsigned short*)sm;    // [128][136]
#pragma unroll
        for (int nb = 0; nb < 16; nb++) {
            int c = nb * 8 + fc;
            sv[c * 136 + lrow]           = __half_as_ushort(__float2half_rn(acc[nb][0]));
            sv[(c + 1) * 136 + lrow]     = __half_as_ushort(__float2half_rn(acc[nb][1]));
            sv[c * 136 + lrow + 8]       = __half_as_ushort(__float2half_rn(acc[nb][2]));
            sv[(c + 1) * 136 + lrow + 8] = __half_as_ushort(__float2half_rn(acc[nb][3]));
        }
        __syncthreads();
#pragma unroll
        for (int m = 0; m < 8; m++) {
            int e = tid + m * 256;               // 2048 uint4 = 128 rows x 16
            int row = e >> 4, q4 = (e & 15) * 8;
            int bh = b * 8 + h0 + (row >> 6), dh = row & 63;
            uint4 v = *(uint4*)(sv + row * 136 + q4);
            *(uint4*)(g_vt + ((size_t)bh * DH_ + dh) * T_ + t0 + q4) = v;
        }
    }

    // ---- fused RMS partials (fp32 accumulators) ----
    float loc[32];
#pragma unroll
    for (int nb = 0; nb < 16; nb++) {
        loc[nb * 2 + 0] = acc[nb][0] * acc[nb][0] + acc[nb][2] * acc[nb][2];
        loc[nb * 2 + 1] = acc[nb][1] * acc[nb][1] + acc[nb][3] * acc[nb][3];
    }
#pragma unroll
    for (int off = 4; off <= 16; off <<= 1)
#pragma unroll
        for (int k = 0; k < 32; k++)
            loc[k] += __shfl_xor_sync(0xffffffffu, loc[k], off);

    __syncthreads();
    float* red = (float*)sm;              // [8][128]
    if (lane < 4) {
#pragma unroll
        for (int nb = 0; nb < 16; nb++) {
            red[wid * 128 + nb * 8 + fc + 0] = loc[nb * 2 + 0];
            red[wid * 128 + nb * 8 + fc + 1] = loc[nb * 2 + 1];
        }
    }
    __syncthreads();
    if (tid < 128) {
        float s = 0.f;
#pragma unroll
        for (int w = 0; w < 8; w++) s += red[w * 128 + tid];
        int nbh = n * 32 + b * 8 + h0 + (tid >> 6);
        g_ssp[(nbh * 16 + blockIdx.x) * 64 + (tid & 63)] = s;
    }
}

// ---------------------------------------------------------------------------
// Kernel 2: mma.sync flash attention — 8 warps x 32 query rows, TQ=256
//   per-key-chunk fused S -> exp2 -> PV; K/V fragments shared across
//   2 row-groups (MMA:LDSM = 4:1); 16 warps/SM via launch_bounds(256,2)
// grid (T/256, 32), block 256
// ---------------------------------------------------------------------------
#define TQ 256
#define TN 64
#define NIT (T_ / TN)
#define SM_Q 0                           // 256 x 144B = 36864 (fp16)
#define SM_KV(s) (36864 + (s) * 18432)   // K (64x144) + V (64x144) per stage
#define SM_SC 92160                      // cs[64] + rv[64] floats
#define SM_TOTAL 92672

__global__ __launch_bounds__(256, 2) void attn_mma_kernel(float* __restrict__ out,
                                                          const float* __restrict__ norm_w)
{
    extern __shared__ char sm[];
    const uint32_t smb = smem_u32(sm);
    const int tid = threadIdx.x, wid = tid >> 5, lane = tid & 31;
    const int bh = blockIdx.y, t0 = blockIdx.x * TQ;

    const __half* qp = g_q + ((size_t)bh * T_ + t0) * DH_;
    const __half* kp = g_k + (size_t)bh * T_ * DH_;
    const __half* vp = g_vt + (size_t)bh * DH_ * T_;

    auto load_kv = [&](int stage, int j0) {
#pragma unroll
        for (int m = 0; m < 2; m++) {
            int cid = tid + m * 256;
            int row = cid >> 3, c = cid & 7;
            cp16(smb + SM_KV(stage) + row * 144 + c * 16,
                 kp + (size_t)(j0 + row) * DH_ + c * 8);
            cp16(smb + SM_KV(stage) + 9216 + row * 144 + c * 16,
                 vp + (size_t)row * T_ + j0 + c * 8);
        }
    };

    // prologue loads: Q (256 rows) + first two KV tiles
#pragma unroll
    for (int m = 0; m < 8; m++) {
        int cid = tid + m * 256;
        int row = cid >> 3, c = cid & 7;
        cp16(smb + SM_Q + row * 144 + c * 16, qp + (size_t)row * DH_ + c * 8);
    }
    load_kv(0, 0);
    CP_COMMIT();
    load_kv(1, TN);
    CP_COMMIT();

    // scale tables from RMS partials (overlaps cp.async latency)
    float* scs = (float*)(sm + SM_SC);        // [64] combined QK scale
    float* rvs = scs + 64;                    // [64] V scale
    if (tid < 64) {
        float nw = norm_w[0];
        float sq = 0.f, sk = 0.f, sv = 0.f;
#pragma unroll
        for (int sl = 0; sl < 16; sl++) {
            sq += g_ssp[((0 * BH_ + bh) * 16 + sl) * 64 + tid];
            sk += g_ssp[((1 * BH_ + bh) * 16 + sl) * 64 + tid];
            sv += g_ssp[((2 * BH_ + bh) * 16 + sl) * 64 + tid];
        }
        float rq = nw * rsqrtf(sq * (1.f / T_) + EPS_);
        float rk = nw * rsqrtf(sk * (1.f / T_) + EPS_);
        scs[tid] = rq * rk * 0.125f * LOG2E_;
        rvs[tid] = nw * rsqrtf(sv * (1.f / T_) + EPS_);
    }

    const int laneRow = ((lane >> 4) & 1) * 8 + (lane & 7);
    const int laneCol = ((lane >> 3) & 1) * 8;
    const int fr = lane >> 2;
    const int fc = (lane & 3) * 2;

    float oAcc[2][8][4] = {};
    float lr[2][2] = {};
    uint32_t qh[2][4][4];                  // [row-group][dh-chunk][4]

    for (int i = 0; i < NIT; i++) {
        if (i + 1 < NIT) { CP_WAIT1(); } else { CP_WAIT0(); }
        __syncthreads();     // tile i ready; also orders scs/rvs writes (i==0)

        if (i + 2 < NIT) { load_kv((i + 2) % 3, (i + 2) * TN); CP_COMMIT(); }

        if (i == 0) {
#pragma unroll
            for (int g = 0; g < 2; g++) {
                const int r = 32 * wid + 16 * g + fr;
#pragma unroll
                for (int ks = 0; ks < 4; ks++) {
                    qh[g][ks][0] = *(const uint32_t*)(sm + SM_Q + r * 144 + (fc + 16 * ks) * 2);
                    qh[g][ks][1] = *(const uint32_t*)(sm + SM_Q + (r + 8) * 144 + (fc + 16 * ks) * 2);
                    qh[g][ks][2] = *(const uint32_t*)(sm + SM_Q + r * 144 + (fc + 8 + 16 * ks) * 2);
                    qh[g][ks][3] = *(const uint32_t*)(sm + SM_Q + (r + 8) * 144 + (fc + 8 + 16 * ks) * 2);
                    // fold combined per-dh scale into Q fragments (once per CTA)
#pragma unroll
                    for (int j = 0; j < 4; j++) {
                        int dh0 = ((j < 2) ? fc : fc + 8) + 16 * ks;
                        float2 c01 = *(float2*)&scs[dh0];
                        __half2 hv = *(__half2*)&qh[g][ks][j];
                        float2 f = __half22float2(hv);
                        qh[g][ks][j] = packh2(f.x * c01.x, f.y * c01.y);
                    }
                }
            }
        }

        const uint32_t kvb = smb + SM_KV(i % 3);

        // per-key-chunk fused S -> exp2 -> PV
#pragma unroll
        for (int p = 0; p < 4; p++) {
            float s[2][2][4] = {};           // [row-group][key-half][4]
#pragma unroll
            for (int ks = 0; ks < 4; ks++) {
                uint32_t b0, b1, b2, b3;
                uint32_t base = kvb + (16 * p + laneRow) * 144 + (16 * ks + laneCol) * 2;
                LDSM4(b0, b1, b2, b3, base);
                MMA16816H(s[0][0], qh[0][ks], b0, b1);
                MMA16816H(s[0][1], qh[0][ks], b2, b3);
                MMA16816H(s[1][0], qh[1][ks], b0, b1);
                MMA16816H(s[1][1], qh[1][ks], b2, b3);
            }

            uint32_t aP[2][4];
#pragma unroll
            for (int g = 0; g < 2; g++) {
                float e00 = ex2f(s[g][0][0]), e01 = ex2f(s[g][0][1]);
                float e02 = ex2f(s[g][0][2]), e03 = ex2f(s[g][0][3]);
                float e10 = ex2f(s[g][1][0]), e11 = ex2f(s[g][1][1]);
                float e12 = ex2f(s[g][1][2]), e13 = ex2f(s[g][1][3]);
                lr[g][0] += e00 + e01 + e10 + e11;
                lr[g][1] += e02 + e03 + e12 + e13;
                aP[g][0] = packh2(e00, e01);
                aP[g][1] = packh2(e02, e03);
                aP[g][2] = packh2(e10, e11);
                aP[g][3] = packh2(e12, e13);
            }

#pragma unroll
            for (int j = 0; j < 4; j++) {
                uint32_t v0, v1, v2, v3;
                uint32_t base = kvb + 9216 + (16 * j + laneRow) * 144
                              + (16 * p + laneCol) * 2;
                LDSM4(v0, v1, v2, v3, base);
                MMA16816H(oAcc[0][2 * j],     aP[0], v0, v1);
                MMA16816H(oAcc[0][2 * j + 1], aP[0], v2, v3);
                MMA16816H(oAcc[1][2 * j],     aP[1], v0, v1);
                MMA16816H(oAcc[1][2 * j + 1], aP[1], v2, v3);
            }
        }
    }

#pragma unroll
    for (int g = 0; g < 2; g++) {
#pragma unroll
        for (int hh = 0; hh < 2; hh++) {
            lr[g][hh] += __shfl_xor_sync(0xffffffffu, lr[g][hh], 1);
            lr[g][hh] += __shfl_xor_sync(0xffffffffu, lr[g][hh], 2);
        }
    }

    // epilogue: two 128-row passes through the [64][132] transpose buffer
    const int b_ = bh >> 3, h_ = bh & 7;
    float* Ot = (float*)sm;              // [64][132]  (disjoint from SM_SC)
    float* ob = out + (size_t)b_ * D_ * T_ + (size_t)h_ * 64 * T_ + t0;

#pragma unroll
    for (int pass = 0; pass < 2; pass++) {
        __syncthreads();
        if ((wid >> 2) == pass) {
            const int lw = wid & 3;
#pragma unroll
            for (int g = 0; g < 2; g++) {
                const float inv0 = 1.f / lr[g][0], inv1 = 1.f / lr[g][1];
                const int rlo = 32 * lw + 16 * g + fr, rhi = rlo + 8;
#pragma unroll
                for (int nb = 0; nb < 8; nb++) {
                    int c = nb * 8 + fc;
                    float rv0 = rvs[c], rv1 = rvs[c + 1];
                    Ot[c * 132 + rlo]       = oAcc[g][nb][0] * inv0 * rv0;
                    Ot[(c + 1) * 132 + rlo] = oAcc[g][nb][1] * inv0 * rv1;
                    Ot[c * 132 + rhi]       = oAcc[g][nb][2] * inv1 * rv0;
                    Ot[(c + 1) * 132 + rhi] = oAcc[g][nb][3] * inv1 * rv1;
                }
            }
        }
        __syncthreads();
#pragma unroll
        for (int k = 0; k < 8; k++) {
            int idx = tid + k * 256;             // 2048 float4 = 64 dh x 32 c4
            int dh = idx >> 5, c4 = idx & 31;
            float4 v = *(float4*)&Ot[dh * 132 + c4 * 4];
            *(float4*)(ob + (size_t)dh * T_ + pass * 128 + c4 * 4) = v;
        }
    }
}

// ---------------------------------------------------------------------------
extern "C" void kernel_launch(void* const* d_in, const int* in_sizes, int n_in,
                              void* d_out, int out_size)
{
    const float* x      = (const float*)d_in[0];
    const float* qkv    = (const float*)d_in[1];
    const float* norm_w = (const float*)d_in[2];
    float* out = (float*)d_out;
    (void)in_sizes; (void)n_in; (void)out_size;

    cudaFuncSetAttribute(attn_mma_kernel, cudaFuncAttributeMaxDynamicSharedMemorySize,
                         SM_TOTAL);
    cudaFuncSetAttribute(qkv_mma_kernel, cudaFuncAttributeMaxDynamicSharedMemorySize,
                         QG_TOTAL);

    xconv_kernel<<<dim3(T_ / 64, D_ / 64, B_), 256>>>(x);
    wconv_kernel<<<24, 256>>>(qkv);
    qkv_mma_kernel<<<dim3(T_ / 128, 48), 256, QG_TOTAL>>>();
    attn_mma_kernel<<<dim3(T_ / TQ, BH_), 256, SM_TOTAL>>>(out, norm_w);
}

// round 17
// speedup vs baseline: 1.0817x; 1.0115x over previous
#include <cuda_runtime.h>
#include <cuda_fp16.h>
#include <cstdint>

// Problem constants
#define B_ 4
#define D_ 512
#define T_ 2048
#define H_ 8
#define DH_ 64
#define BH_ 32        // B*H
#define NBH_ 96       // 3*B*H
#define NEG_SLOPE 0.2f
#define EPS_ 1e-6f
#define LOG2E_ 1.44269504088896f

// ---------------------------------------------------------------------------
// Scratch (__device__ globals; allocation-free rule)
// ---------------------------------------------------------------------------
__device__ float g_ssp[NBH_ * 16 * 64];             // rms partials [nbh][tblk][dh]
// fp16 operands (all RAW, unscaled; scales applied inside attention)
__device__ __half g_q[(size_t)BH_ * T_ * DH_];      // Q raw fp16 [bh][t][dh]
__device__ __half g_k[(size_t)BH_ * T_ * DH_];      // K raw fp16
__device__ __half g_vt[(size_t)BH_ * DH_ * T_];     // V^T raw fp16
__device__ __half g_xh[(size_t)B_ * T_ * D_];       // [b][t][d] lrelu'd
__device__ __half g_wh[(size_t)24 * DH_ * D_];      // [n*8+h][dh][d]

// ---------------------------------------------------------------------------
// PTX helpers
// ---------------------------------------------------------------------------
__device__ __forceinline__ uint32_t smem_u32(const void* p) {
    uint32_t a;
    asm("{ .reg .u64 t; cvta.to.shared.u64 t, %1; cvt.u32.u64 %0, t; }"
        : "=r"(a) : "l"(p));
    return a;
}
__device__ __forceinline__ void cp16(uint32_t dst, const void* src) {
    asm volatile("cp.async.cg.shared.global [%0], [%1], 16;"
                 :: "r"(dst), "l"(src));
}
#define CP_COMMIT() asm volatile("cp.async.commit_group;" ::: "memory")
#define CP_WAIT1()  asm volatile("cp.async.wait_group 1;" ::: "memory")
#define CP_WAIT0()  asm volatile("cp.async.wait_group 0;" ::: "memory")

#define LDSM4(r0, r1, r2, r3, addr) \
    asm volatile("ldmatrix.sync.aligned.m8n8.x4.shared.b16 {%0,%1,%2,%3}, [%4];" \
        : "=r"(r0), "=r"(r1), "=r"(r2), "=r"(r3) : "r"(addr))

#define MMA16816H(c, a, b0, b1) \
    asm volatile("mma.sync.aligned.m16n8k16.row.col.f32.f16.f16.f32 " \
        "{%0,%1,%2,%3}, {%4,%5,%6,%7}, {%8,%9}, {%0,%1,%2,%3};" \
        : "+f"((c)[0]), "+f"((c)[1]), "+f"((c)[2]), "+f"((c)[3]) \
        : "r"((a)[0]), "r"((a)[1]), "r"((a)[2]), "r"((a)[3]), "r"(b0), "r"(b1))

// pack (x -> low, y -> high) as f16x2
__device__ __forceinline__ uint32_t packh2(float x, float y) {
    uint32_t r;
    asm("cvt.rn.f16x2.f32 %0, %1, %2;" : "=r"(r) : "f"(y), "f"(x));
    return r;
}
// elementwise 2^x on packed f16x2
__device__ __forceinline__ uint32_t h2ex2(uint32_t x) {
    uint32_t r;
    asm("ex2.approx.f16x2 %0, %1;" : "=r"(r) : "r"(x));
    return r;
}

// ---------------------------------------------------------------------------
// Kernel 1a: x convert — leaky-relu + fp16 + transpose to [b][t][d]
// grid (T/64, D/64, B), block 256
// ---------------------------------------------------------------------------
__global__ __launch_bounds__(256) void xconv_kernel(const float* __restrict__ x)
{
    __shared__ unsigned short shi[64][66];
    const int t0 = blockIdx.x * 64, d0 = blockIdx.y * 64, b = blockIdx.z;
    const int tid = threadIdx.x;
    const float* xb = x + (size_t)b * D_ * T_;

#pragma unroll
    for (int k = 0; k < 16; k++) {
        int idx = tid + k * 256;
        int r = idx >> 6, c = idx & 63;        // r = d row, c = t col
        float v = xb[(size_t)(d0 + r) * T_ + t0 + c];
        v = (v >= 0.f) ? v : NEG_SLOPE * v;
        shi[c][r] = __half_as_ushort(__float2half_rn(v));   // transposed [t][d]
    }
    __syncthreads();
#pragma unroll
    for (int k = 0; k < 8; k++) {
        int idx = tid + k * 256;
        int t = idx >> 5, u = idx & 31;
        size_t go = ((size_t)b * T_ + t0 + t) * D_ + d0 + u * 2;
        *(uint32_t*)(g_xh + go) = shi[t][u * 2] | ((uint32_t)shi[t][u * 2 + 1] << 16);
    }
}

// ---------------------------------------------------------------------------
// Kernel 1b: weight convert — fp16 + transpose to [nh][dh][d]; grid 24
// ---------------------------------------------------------------------------
__global__ __launch_bounds__(256) void wconv_kernel(const float* __restrict__ w)
{
    __shared__ unsigned short shi[64][66];
    const int nh = blockIdx.x, tid = threadIdx.x;
    const float* wb = w + (size_t)nh * D_ * DH_;

    for (int d0 = 0; d0 < D_; d0 += 64) {
#pragma unroll
        for (int k = 0; k < 16; k++) {
            int idx = tid + k * 256;
            int r = idx >> 6, c = idx & 63;
            shi[c][r] = __half_as_ushort(__float2half_rn(wb[(size_t)(d0 + r) * DH_ + c]));
        }
        __syncthreads();
#pragma unroll
        for (int k = 0; k < 8; k++) {
            int idx = tid + k * 256;
            int dh = idx >> 5, u = idx & 31;
            size_t go = ((size_t)nh * DH_ + dh) * D_ + d0 + u * 2;
            *(uint32_t*)(g_wh + go) = shi[dh][u * 2] | ((uint32_t)shi[dh][u * 2 + 1] << 16);
        }
        __syncthreads();
    }
}

// ---------------------------------------------------------------------------
// Kernel 1c: QKV projection, 2 heads per CTA (128x128 tile) + fused RMS
// grid (T/128, 48): y = n*16 + b*4 + hpair;  block 256 (8 warps x 16 rows)
// ---------------------------------------------------------------------------
#define QG_SA(buf) ((buf) * 18432)           // A fp16 (128 x 144B)
#define QG_SB(buf) (36864 + (buf) * 18432)   // B fp16 (128 x 144B)
#define QG_TOTAL 73728

__global__ __launch_bounds__(256, 2) void qkv_mma_kernel()
{
    extern __shared__ char sm[];
    const uint32_t smb = smem_u32(sm);
    const int tid = threadIdx.x, wid = tid >> 5, lane = tid & 31;
    const int yi = blockIdx.y;                   // n*16 + b*4 + hpair
    const int n = yi >> 4, b = (yi >> 2) & 3, h0 = (yi & 3) * 2;
    const int t0 = blockIdx.x * 128;

    const __half* xh = g_xh + ((size_t)b * T_ + t0) * D_;
    const __half* wh = g_wh + (size_t)(n * 8 + h0) * DH_ * D_;  // 128 rows = 2 heads

    auto load_a = [&](int buf, int d0) {
#pragma unroll
        for (int m = 0; m < 4; m++) {
            int cid = tid + m * 256;
            int row = cid >> 3, c = cid & 7;
            cp16(smb + QG_SA(buf) + row * 144 + c * 16,
                 xh + (size_t)row * D_ + d0 + c * 8);
        }
    };
    auto load_b = [&](int buf, int d0) {
#pragma unroll
        for (int m = 0; m < 4; m++) {
            int cid = tid + m * 256;
            int row = cid >> 3, c = cid & 7;   // row 0..127: 2 heads x 64 dh
            cp16(smb + QG_SB(buf) + row * 144 + c * 16,
                 wh + (size_t)row * D_ + d0 + c * 8);
        }
    };

    load_a(0, 0); load_b(0, 0);
    CP_COMMIT();

    const int laneRowA = lane & 15;
    const int laneColA = (lane >> 4) * 8;
    const int laneRowB = ((lane >> 4) & 1) * 8 + (lane & 7);
    const int laneColB = ((lane >> 3) & 1) * 8;
    const int fr = lane >> 2, fc = (lane & 3) * 2;

    float acc[16][4] = {};

    for (int i = 0; i < 8; i++) {
        const int buf = i & 1;
        if (i + 1 < 8) { load_a(buf ^ 1, (i + 1) * 64); load_b(buf ^ 1, (i + 1) * 64); CP_COMMIT(); }
        if (i + 1 < 8) { CP_WAIT1(); } else { CP_WAIT0(); }
        __syncthreads();

#pragma unroll
        for (int ks = 0; ks < 4; ks++) {
            uint32_t ah[4];
            uint32_t abase = smb + QG_SA(buf) + (16 * wid + laneRowA) * 144
                           + (ks * 16 + laneColA) * 2;
            LDSM4(ah[0], ah[1], ah[2], ah[3], abase);
#pragma unroll
            for (int p = 0; p < 8; p++) {
                uint32_t h0r, h1r, h2r, h3r;
                uint32_t bbase = smb + QG_SB(buf) + (16 * p + laneRowB) * 144
                               + (ks * 16 + laneColB) * 2;
                LDSM4(h0r, h1r, h2r, h3r, bbase);
                MMA16816H(acc[2 * p],     ah, h0r, h1r);
                MMA16816H(acc[2 * p + 1], ah, h2r, h3r);
            }
        }
        __syncthreads();
    }

    const int lrow = 16 * wid + fr;              // local row 0..127

    // ---- epilogue: raw fp16 outputs (cols 0..63 -> h0, 64..127 -> h0+1) ----
    if (n < 2) {
        __half* base = (n == 0 ? g_q : g_k);
        __half* dst0 = base + ((size_t)(b * 8 + h0) * T_ + t0 + lrow) * DH_;
        __half* dst1 = base + ((size_t)(b * 8 + h0 + 1) * T_ + t0 + lrow) * DH_;
#pragma unroll
        for (int nb = 0; nb < 8; nb++) {
            int col = nb * 8 + fc;
            *(uint32_t*)(dst0 + col)           = packh2(acc[nb][0], acc[nb][1]);
            *(uint32_t*)(dst0 + 8 * DH_ + col) = packh2(acc[nb][2], acc[nb][3]);
            *(uint32_t*)(dst1 + col)           = packh2(acc[nb + 8][0], acc[nb + 8][1]);
            *(uint32_t*)(dst1 + 8 * DH_ + col) = packh2(acc[nb + 8][2], acc[nb + 8][3]);
        }
    } else {
        // transpose both heads to [dh][t] via smem (stride 136 ushorts)
        unsigned short* sv = (unsigned short*)sm;    // [128][136]
#pragma unroll
        for (int nb = 0; nb < 16; nb++) {
            int c = nb * 8 + fc;
            sv[c * 136 + lrow]           = __half_as_ushort(__float2half_rn(acc[nb][0]));
            sv[(c + 1) * 136 + lrow]     = __half_as_ushort(__float2half_rn(acc[nb][1]));
            sv[c * 136 + lrow + 8]       = __half_as_ushort(__float2half_rn(acc[nb][2]));
            sv[(c + 1) * 136 + lrow + 8] = __half_as_ushort(__float2half_rn(acc[nb][3]));
        }
        __syncthreads();
#pragma unroll
        for (int m = 0; m < 8; m++) {
            int e = tid + m * 256;               // 2048 uint4 = 128 rows x 16
            int row = e >> 4, q4 = (e & 15) * 8;
            int bh = b * 8 + h0 + (row >> 6), dh = row & 63;
            uint4 v = *(uint4*)(sv + row * 136 + q4);
            *(uint4*)(g_vt + ((size_t)bh * DH_ + dh) * T_ + t0 + q4) = v;
        }
    }

    // ---- fused RMS partials (fp32 accumulators) ----
    float loc[32];
#pragma unroll
    for (int nb = 0; nb < 16; nb++) {
        loc[nb * 2 + 0] = acc[nb][0] * acc[nb][0] + acc[nb][2] * acc[nb][2];
        loc[nb * 2 + 1] = acc[nb][1] * acc[nb][1] + acc[nb][3] * acc[nb][3];
    }
#pragma unroll
    for (int off = 4; off <= 16; off <<= 1)
#pragma unroll
        for (int k = 0; k < 32; k++)
            loc[k] += __shfl_xor_sync(0xffffffffu, loc[k], off);

    __syncthreads();
    float* red = (float*)sm;              // [8][128]
    if (lane < 4) {
#pragma unroll
        for (int nb = 0; nb < 16; nb++) {
            red[wid * 128 + nb * 8 + fc + 0] = loc[nb * 2 + 0];
            red[wid * 128 + nb * 8 + fc + 1] = loc[nb * 2 + 1];
        }
    }
    __syncthreads();
    if (tid < 128) {
        float s = 0.f;
#pragma unroll
        for (int w = 0; w < 8; w++) s += red[w * 128 + tid];
        int nbh = n * 32 + b * 8 + h0 + (tid >> 6);
        g_ssp[(nbh * 16 + blockIdx.x) * 64 + (tid & 63)] = s;
    }
}

// ---------------------------------------------------------------------------
// Kernel 2: mma.sync flash attention — 8 warps x 32 query rows, TQ=256
//   per-key-chunk fused S -> f16x2 exp2 -> PV;  row-sum l via ones-MMA;
//   K/V fragments shared across 2 row-groups (MMA:LDSM = 4:1)
// grid (T/256, 32), block 256
// ---------------------------------------------------------------------------
#define TQ 256
#define TN 64
#define NIT (T_ / TN)
#define SM_Q 0                           // 256 x 144B = 36864 (fp16)
#define SM_KV(s) (36864 + (s) * 18432)   // K (64x144) + V (64x144) per stage
#define SM_SC 92160                      // cs[64] + rv[64] floats
#define SM_TOTAL 92672

__global__ __launch_bounds__(256, 2) void attn_mma_kernel(float* __restrict__ out,
                                                          const float* __restrict__ norm_w)
{
    extern __shared__ char sm[];
    const uint32_t smb = smem_u32(sm);
    const int tid = threadIdx.x, wid = tid >> 5, lane = tid & 31;
    const int bh = blockIdx.y, t0 = blockIdx.x * TQ;

    const __half* qp = g_q + ((size_t)bh * T_ + t0) * DH_;
    const __half* kp = g_k + (size_t)bh * T_ * DH_;
    const __half* vp = g_vt + (size_t)bh * DH_ * T_;

    auto load_kv = [&](int stage, int j0) {
#pragma unroll
        for (int m = 0; m < 2; m++) {
            int cid = tid + m * 256;
            int row = cid >> 3, c = cid & 7;
            cp16(smb + SM_KV(stage) + row * 144 + c * 16,
                 kp + (size_t)(j0 + row) * DH_ + c * 8);
            cp16(smb + SM_KV(stage) + 9216 + row * 144 + c * 16,
                 vp + (size_t)row * T_ + j0 + c * 8);
        }
    };

    // prologue loads: Q (256 rows) + first two KV tiles
#pragma unroll
    for (int m = 0; m < 8; m++) {
        int cid = tid + m * 256;
        int row = cid >> 3, c = cid & 7;
        cp16(smb + SM_Q + row * 144 + c * 16, qp + (size_t)row * DH_ + c * 8);
    }
    load_kv(0, 0);
    CP_COMMIT();
    load_kv(1, TN);
    CP_COMMIT();

    // scale tables from RMS partials (overlaps cp.async latency)
    float* scs = (float*)(sm + SM_SC);        // [64] combined QK scale
    float* rvs = scs + 64;                    // [64] V scale
    if (tid < 64) {
        float nw = norm_w[0];
        float sq = 0.f, sk = 0.f, sv = 0.f;
#pragma unroll
        for (int sl = 0; sl < 16; sl++) {
            sq += g_ssp[((0 * BH_ + bh) * 16 + sl) * 64 + tid];
            sk += g_ssp[((1 * BH_ + bh) * 16 + sl) * 64 + tid];
            sv += g_ssp[((2 * BH_ + bh) * 16 + sl) * 64 + tid];
        }
        float rq = nw * rsqrtf(sq * (1.f / T_) + EPS_);
        float rk = nw * rsqrtf(sk * (1.f / T_) + EPS_);
        scs[tid] = rq * rk * 0.125f * LOG2E_;
        rvs[tid] = nw * rsqrtf(sv * (1.f / T_) + EPS_);
    }

    const int laneRow = ((lane >> 4) & 1) * 8 + (lane & 7);
    const int laneCol = ((lane >> 3) & 1) * 8;
    const int fr = lane >> 2;
    const int fc = (lane & 3) * 2;

    const uint32_t ONES2 = 0x3C003C00u;    // f16x2 (1.0, 1.0)

    float oAcc[2][8][4] = {};
    float lAcc[2][4] = {};                 // ones-MMA accumulators (row sums)
    uint32_t qh[2][4][4];                  // [row-group][dh-chunk][4]

    for (int i = 0; i < NIT; i++) {
        if (i + 1 < NIT) { CP_WAIT1(); } else { CP_WAIT0(); }
        __syncthreads();     // tile i ready; also orders scs/rvs writes (i==0)

        if (i + 2 < NIT) { load_kv((i + 2) % 3, (i + 2) * TN); CP_COMMIT(); }

        if (i == 0) {
#pragma unroll
            for (int g = 0; g < 2; g++) {
                const int r = 32 * wid + 16 * g + fr;
#pragma unroll
                for (int ks = 0; ks < 4; ks++) {
                    qh[g][ks][0] = *(const uint32_t*)(sm + SM_Q + r * 144 + (fc + 16 * ks) * 2);
                    qh[g][ks][1] = *(const uint32_t*)(sm + SM_Q + (r + 8) * 144 + (fc + 16 * ks) * 2);
                    qh[g][ks][2] = *(const uint32_t*)(sm + SM_Q + r * 144 + (fc + 8 + 16 * ks) * 2);
                    qh[g][ks][3] = *(const uint32_t*)(sm + SM_Q + (r + 8) * 144 + (fc + 8 + 16 * ks) * 2);
                    // fold combined per-dh scale into Q fragments (once per CTA)
#pragma unroll
                    for (int j = 0; j < 4; j++) {
                        int dh0 = ((j < 2) ? fc : fc + 8) + 16 * ks;
                        float2 c01 = *(float2*)&scs[dh0];
                        __half2 hv = *(__half2*)&qh[g][ks][j];
                        float2 f = __half22float2(hv);
                        qh[g][ks][j] = packh2(f.x * c01.x, f.y * c01.y);
                    }
                }
            }
        }

        const uint32_t kvb = smb + SM_KV(i % 3);

        // per-key-chunk fused S -> f16x2 exp2 -> PV  (+ l via ones-MMA)
#pragma unroll
        for (int p = 0; p < 4; p++) {
            float s[2][2][4] = {};           // [row-group][key-half][4]
#pragma unroll
            for (int ks = 0; ks < 4; ks++) {
                uint32_t b0, b1, b2, b3;
                uint32_t base = kvb + (16 * p + laneRow) * 144 + (16 * ks + laneCol) * 2;
                LDSM4(b0, b1, b2, b3, base);
                MMA16816H(s[0][0], qh[0][ks], b0, b1);
                MMA16816H(s[0][1], qh[0][ks], b2, b3);
                MMA16816H(s[1][0], qh[1][ks], b0, b1);
                MMA16816H(s[1][1], qh[1][ks], b2, b3);
            }

            uint32_t aP[2][4];
#pragma unroll
            for (int g = 0; g < 2; g++) {
                aP[g][0] = h2ex2(packh2(s[g][0][0], s[g][0][1]));
                aP[g][1] = h2ex2(packh2(s[g][0][2], s[g][0][3]));
                aP[g][2] = h2ex2(packh2(s[g][1][0], s[g][1][1]));
                aP[g][3] = h2ex2(packh2(s[g][1][2], s[g][1][3]));
            }
            // l row-sums: P x ones (exact fp32 accumulation of the fp16 P)
            MMA16816H(lAcc[0], aP[0], ONES2, ONES2);
            MMA16816H(lAcc[1], aP[1], ONES2, ONES2);

#pragma unroll
            for (int j = 0; j < 4; j++) {
                uint32_t v0, v1, v2, v3;
                uint32_t base = kvb + 9216 + (16 * j + laneRow) * 144
                              + (16 * p + laneCol) * 2;
                LDSM4(v0, v1, v2, v3, base);
                MMA16816H(oAcc[0][2 * j],     aP[0], v0, v1);
                MMA16816H(oAcc[0][2 * j + 1], aP[0], v2, v3);
                MMA16816H(oAcc[1][2 * j],     aP[1], v0, v1);
                MMA16816H(oAcc[1][2 * j + 1], aP[1], v2, v3);
            }
        }
    }

    // epilogue: two 128-row passes through the [64][132] transpose buffer
    const int b_ = bh >> 3, h_ = bh & 7;
    float* Ot = (float*)sm;              // [64][132]  (disjoint from SM_SC)
    float* ob = out + (size_t)b_ * D_ * T_ + (size_t)h_ * 64 * T_ + t0;

#pragma unroll
    for (int pass = 0; pass < 2; pass++) {
        __syncthreads();
        if ((wid >> 2) == pass) {
            const int lw = wid & 3;
#pragma unroll
            for (int g = 0; g < 2; g++) {
                const float inv0 = 1.f / lAcc[g][0], inv1 = 1.f / lAcc[g][2];
                const int rlo = 32 * lw + 16 * g + fr, rhi = rlo + 8;
#pragma unroll
                for (int nb = 0; nb < 8; nb++) {
                    int c = nb * 8 + fc;
                    float rv0 = rvs[c], rv1 = rvs[c + 1];
                    Ot[c * 132 + rlo]       = oAcc[g][nb][0] * inv0 * rv0;
                    Ot[(c + 1) * 132 + rlo] = oAcc[g][nb][1] * inv0 * rv1;
                    Ot[c * 132 + rhi]       = oAcc[g][nb][2] * inv1 * rv0;
                    Ot[(c + 1) * 132 + rhi] = oAcc[g][nb][3] * inv1 * rv1;
                }
            }
        }
        __syncthreads();
#pragma unroll
        for (int k = 0; k < 8; k++) {
            int idx = tid + k * 256;             // 2048 float4 = 64 dh x 32 c4
            int dh = idx >> 5, c4 = idx & 31;
            float4 v = *(float4*)&Ot[dh * 132 + c4 * 4];
            *(float4*)(ob + (size_t)dh * T_ + pass * 128 + c4 * 4) = v;
        }
    }
}

// ---------------------------------------------------------------------------
extern "C" void kernel_launch(void* const* d_in, const int* in_sizes, int n_in,
                              void* d_out, int out_size)
{
    const float* x      = (const float*)d_in[0];
    const float* qkv    = (const float*)d_in[1];
    const float* norm_w = (const float*)d_in[2];
    float* out = (float*)d_out;
    (void)in_sizes; (void)n_in; (void)out_size;

    cudaFuncSetAttribute(attn_mma_kernel, cudaFuncAttributeMaxDynamicSharedMemorySize,
                         SM_TOTAL);
    cudaFuncSetAttribute(qkv_mma_kernel, cudaFuncAttributeMaxDynamicSharedMemorySize,
                         QG_TOTAL);

    xconv_kernel<<<dim3(T_ / 64, D_ / 64, B_), 256>>>(x);
    wconv_kernel<<<24, 256>>>(qkv);
    qkv_mma_kernel<<<dim3(T_ / 128, 48), 256, QG_TOTAL>>>();
    attn_mma_kernel<<<dim3(T_ / TQ, BH_), 256, SM_TOTAL>>>(out, norm_w);
}